// round 1
// baseline (speedup 1.0000x reference)
#include <cuda_runtime.h>
#include <cuda_bf16.h>
#include <cstddef>

// Problem constants (fixed by the dataset)
constexpr int NN = 40000;   // nodes
constexpr int EE = 640000;  // edges
constexpr int DD = 128;     // feature dim
constexpr int HH = 8;       // heads
constexpr int D4 = 512;     // FFN hidden

// ---------------------------------------------------------------------------
// Device scratch (zero-init .bss; no allocations anywhere)
// ---------------------------------------------------------------------------
__device__ float g_q  [(size_t)NN * DD];
__device__ float g_k  [(size_t)NN * DD];
__device__ float g_v  [(size_t)NN * DD];
__device__ float g_sexp[(size_t)EE * HH];
__device__ float g_ssum[(size_t)NN * HH];
__device__ float g_ft2 [(size_t)NN * DD];
__device__ float g_rst [(size_t)NN * DD];
__device__ float g_h1  [(size_t)NN * D4];
__device__ float g_ffn [(size_t)NN * DD];

// ---------------------------------------------------------------------------
// Zero scratch used by atomics (must be re-zeroed every launch: graph replays)
// ---------------------------------------------------------------------------
__global__ void zero_kernel(float* __restrict__ a, int na,
                            float* __restrict__ b, int nb)
{
    int stride = gridDim.x * blockDim.x;
    for (int j = blockIdx.x * blockDim.x + threadIdx.x; j < na; j += stride) a[j] = 0.f;
    for (int j = blockIdx.x * blockDim.x + threadIdx.x; j < nb; j += stride) b[j] = 0.f;
}

// ---------------------------------------------------------------------------
// fp32 tiled GEMM: C[M,N] = A[M,K] @ B[K,N] (+bias)(+PReLU)
// 64x64 tile per 256-thread block, 4x4 microtile, K-chunk 16.
// M % 64 == 0, N % 64 == 0, K % 16 == 0 guaranteed by problem shapes.
// MODE: 0 = plain, 1 = +bias, 2 = +bias then PReLU(per-channel)
// ---------------------------------------------------------------------------
template <int MODE>
__global__ void __launch_bounds__(256)
gemm_tile(const float* __restrict__ A, const float* __restrict__ B,
          const float* __restrict__ bias, const float* __restrict__ pw,
          float* __restrict__ C, int M, int N, int K)
{
    __shared__ float As[16][68];
    __shared__ float Bs[16][68];

    const int tid = threadIdx.x;
    const int tx = tid & 15;
    const int ty = tid >> 4;
    const int m0 = blockIdx.y * 64;
    const int n0 = blockIdx.x * 64;

    // A-load mapping: each thread loads one float4 (64 rows x 16 k per block)
    const int am = tid >> 2;          // 0..63
    const int ak = (tid & 3) * 4;     // 0,4,8,12
    // B-load mapping: 4 rows of 64 floats per pass
    const int bn  = tid & 63;
    const int bk0 = tid >> 6;         // 0..3

    float acc[4][4];
#pragma unroll
    for (int i = 0; i < 4; i++)
#pragma unroll
        for (int j = 0; j < 4; j++) acc[i][j] = 0.f;

    for (int k0 = 0; k0 < K; k0 += 16) {
        float4 av = *(const float4*)(A + (size_t)(m0 + am) * K + k0 + ak);
        As[ak + 0][am] = av.x;
        As[ak + 1][am] = av.y;
        As[ak + 2][am] = av.z;
        As[ak + 3][am] = av.w;
#pragma unroll
        for (int r = 0; r < 4; r++) {
            Bs[bk0 + r * 4][bn] = B[(size_t)(k0 + bk0 + r * 4) * N + n0 + bn];
        }
        __syncthreads();

#pragma unroll
        for (int kk = 0; kk < 16; kk++) {
            float a0 = As[kk][ty * 4 + 0];
            float a1 = As[kk][ty * 4 + 1];
            float a2 = As[kk][ty * 4 + 2];
            float a3 = As[kk][ty * 4 + 3];
            float b0 = Bs[kk][tx * 4 + 0];
            float b1 = Bs[kk][tx * 4 + 1];
            float b2 = Bs[kk][tx * 4 + 2];
            float b3 = Bs[kk][tx * 4 + 3];
            acc[0][0] += a0 * b0; acc[0][1] += a0 * b1; acc[0][2] += a0 * b2; acc[0][3] += a0 * b3;
            acc[1][0] += a1 * b0; acc[1][1] += a1 * b1; acc[1][2] += a1 * b2; acc[1][3] += a1 * b3;
            acc[2][0] += a2 * b0; acc[2][1] += a2 * b1; acc[2][2] += a2 * b2; acc[2][3] += a2 * b3;
            acc[3][0] += a3 * b0; acc[3][1] += a3 * b1; acc[3][2] += a3 * b2; acc[3][3] += a3 * b3;
        }
        __syncthreads();
    }

#pragma unroll
    for (int i = 0; i < 4; i++) {
        const int row = m0 + ty * 4 + i;
#pragma unroll
        for (int j = 0; j < 4; j++) {
            const int col = n0 + tx * 4 + j;
            float val = acc[i][j];
            if (MODE >= 1) val += bias[col];
            if (MODE == 2) val = (val >= 0.f) ? val : pw[col] * val;
            C[(size_t)row * N + col] = val;
        }
    }
}

// ---------------------------------------------------------------------------
// Edge pass 1: per-edge per-head scores -> exp -> store + segment-sum(dst)
// One warp per edge; lane l handles float4 [4l,4l+4); head = lane/4.
// Softmax max-shift is omitted: scores have std ~0.018 (|s| < ~0.15), the
// shifted/unshifted forms are mathematically identical after normalization.
// ---------------------------------------------------------------------------
__global__ void edge_score_kernel(const float* __restrict__ q,
                                  const float* __restrict__ k,
                                  const int* __restrict__ src,
                                  const int* __restrict__ dst,
                                  float* __restrict__ sexp,
                                  float* __restrict__ ssum)
{
    const int e = (int)((blockIdx.x * blockDim.x + threadIdx.x) >> 5);
    const int lane = threadIdx.x & 31;
    if (e >= EE) return;
    const int s = __ldg(src + e);
    const int d = __ldg(dst + e);

    float4 kv = *(const float4*)(k + (size_t)s * DD + lane * 4);
    float4 qv = *(const float4*)(q + (size_t)d * DD + lane * 4);
    float dot = kv.x * qv.x + kv.y * qv.y + kv.z * qv.z + kv.w * qv.w;
    dot += __shfl_xor_sync(0xffffffffu, dot, 1);
    dot += __shfl_xor_sync(0xffffffffu, dot, 2);

    if ((lane & 3) == 0) {
        const int h = lane >> 2;
        // 1/sqrt(DH*H) = 1/sqrt(128)
        float ex = __expf(dot * 0.08838834764831845f);
        sexp[(size_t)e * HH + h] = ex;
        atomicAdd(&ssum[(size_t)d * HH + h], ex);
    }
}

// ---------------------------------------------------------------------------
// Edge pass 2: a = sexp/ssum[dst]; ft2[dst] += a * v[src]
// ---------------------------------------------------------------------------
__global__ void edge_aggr_kernel(const float* __restrict__ v,
                                 const int* __restrict__ src,
                                 const int* __restrict__ dst,
                                 const float* __restrict__ sexp,
                                 const float* __restrict__ ssum,
                                 float* __restrict__ ft2)
{
    const int e = (int)((blockIdx.x * blockDim.x + threadIdx.x) >> 5);
    const int lane = threadIdx.x & 31;
    if (e >= EE) return;
    const int s = __ldg(src + e);
    const int d = __ldg(dst + e);
    const int h = lane >> 2;

    const float a = __ldg(sexp + (size_t)e * HH + h) / __ldg(ssum + (size_t)d * HH + h);
    float4 vv = *(const float4*)(v + (size_t)s * DD + lane * 4);
    float* out = ft2 + (size_t)d * DD + lane * 4;
    atomicAdd(out + 0, vv.x * a);
    atomicAdd(out + 1, vv.y * a);
    atomicAdd(out + 2, vv.z * a);
    atomicAdd(out + 3, vv.w * a);
}

// ---------------------------------------------------------------------------
// LayerNorm(X + Y) * g + b; one warp per 128-float row
// ---------------------------------------------------------------------------
__global__ void ln_add_kernel(const float* __restrict__ X,
                              const float* __restrict__ Y,
                              const float* __restrict__ g,
                              const float* __restrict__ b,
                              float* __restrict__ out)
{
    const int row = (int)((blockIdx.x * blockDim.x + threadIdx.x) >> 5);
    const int lane = threadIdx.x & 31;
    if (row >= NN) return;

    float4 x = *(const float4*)(X + (size_t)row * DD + lane * 4);
    float4 y = *(const float4*)(Y + (size_t)row * DD + lane * 4);
    x.x += y.x; x.y += y.y; x.z += y.z; x.w += y.w;

    float s  = x.x + x.y + x.z + x.w;
    float ss = x.x * x.x + x.y * x.y + x.z * x.z + x.w * x.w;
#pragma unroll
    for (int o = 16; o > 0; o >>= 1) {
        s  += __shfl_xor_sync(0xffffffffu, s,  o);
        ss += __shfl_xor_sync(0xffffffffu, ss, o);
    }
    const float mu  = s * (1.f / DD);
    const float var = ss * (1.f / DD) - mu * mu;
    const float rs  = rsqrtf(var + 1e-5f);

    float4 gv = *(const float4*)(g + lane * 4);
    float4 bv = *(const float4*)(b + lane * 4);
    float4 o4;
    o4.x = (x.x - mu) * rs * gv.x + bv.x;
    o4.y = (x.y - mu) * rs * gv.y + bv.y;
    o4.z = (x.z - mu) * rs * gv.z + bv.z;
    o4.w = (x.w - mu) * rs * gv.w + bv.w;
    *(float4*)(out + (size_t)row * DD + lane * 4) = o4;
}

// ---------------------------------------------------------------------------
// Launch
// ---------------------------------------------------------------------------
extern "C" void kernel_launch(void* const* d_in, const int* in_sizes, int n_in,
                              void* d_out, int out_size)
{
    const float* feat  = (const float*)d_in[0];
    const int*   src   = (const int*)  d_in[1];
    const int*   dst   = (const int*)  d_in[2];
    const float* Wq    = (const float*)d_in[3];
    const float* Wk    = (const float*)d_in[4];
    const float* Wv    = (const float*)d_in[5];
    const float* ln1_g = (const float*)d_in[6];
    const float* ln1_b = (const float*)d_in[7];
    const float* ln2_g = (const float*)d_in[8];
    const float* ln2_b = (const float*)d_in[9];
    const float* W1    = (const float*)d_in[10];
    const float* b1    = (const float*)d_in[11];
    const float* pw    = (const float*)d_in[12];
    const float* W2    = (const float*)d_in[13];
    const float* b2    = (const float*)d_in[14];
    float* out = (float*)d_out;

    float *q, *k, *v, *sexp, *ssum, *ft2, *rst, *h1, *ffn;
    cudaGetSymbolAddress((void**)&q,    g_q);
    cudaGetSymbolAddress((void**)&k,    g_k);
    cudaGetSymbolAddress((void**)&v,    g_v);
    cudaGetSymbolAddress((void**)&sexp, g_sexp);
    cudaGetSymbolAddress((void**)&ssum, g_ssum);
    cudaGetSymbolAddress((void**)&ft2,  g_ft2);
    cudaGetSymbolAddress((void**)&rst,  g_rst);
    cudaGetSymbolAddress((void**)&h1,   g_h1);
    cudaGetSymbolAddress((void**)&ffn,  g_ffn);

    // 1) zero atomic accumulators (every call: graph replays reuse scratch)
    zero_kernel<<<2048, 256>>>(ssum, NN * HH, ft2, NN * DD);

    // 2) QKV projections: [40000,128] @ [128,128]
    dim3 gqkv(DD / 64, NN / 64);
    gemm_tile<0><<<gqkv, 256>>>(feat, Wq, nullptr, nullptr, q, NN, DD, DD);
    gemm_tile<0><<<gqkv, 256>>>(feat, Wk, nullptr, nullptr, k, NN, DD, DD);
    gemm_tile<0><<<gqkv, 256>>>(feat, Wv, nullptr, nullptr, v, NN, DD, DD);

    // 3) edge scores + segment-sum of exp
    const int edge_blocks = (EE * 32 + 255) / 256;
    edge_score_kernel<<<edge_blocks, 256>>>(q, k, src, dst, sexp, ssum);

    // 4) normalized weighted aggregation into ft2
    edge_aggr_kernel<<<edge_blocks, 256>>>(v, src, dst, sexp, ssum, ft2);

    // 5) rst = LN(ft2 + feat)
    const int ln_blocks = (NN * 32 + 255) / 256;
    ln_add_kernel<<<ln_blocks, 256>>>(ft2, feat, ln1_g, ln1_b, rst);

    // 6) FFN1: h1 = PReLU(rst @ W1 + b1)   [40000,128]@[128,512]
    gemm_tile<2><<<dim3(D4 / 64, NN / 64), 256>>>(rst, W1, b1, pw, h1, NN, D4, DD);

    // 7) FFN2: ffn = h1 @ W2 + b2          [40000,512]@[512,128]
    gemm_tile<1><<<dim3(DD / 64, NN / 64), 256>>>(h1, W2, b2, nullptr, ffn, NN, DD, D4);

    // 8) out = LN(rst + ffn)
    ln_add_kernel<<<ln_blocks, 256>>>(rst, ffn, ln2_g, ln2_b, out);
}

// round 3
// speedup vs baseline: 1.5876x; 1.5876x over previous
#include <cuda_runtime.h>
#include <cuda_bf16.h>
#include <cstdint>
#include <cstddef>

constexpr int NN = 40000;   // nodes
constexpr int EE = 640000;  // edges
constexpr int DD = 128;     // feature dim
constexpr int HH = 8;       // heads
constexpr int D4 = 512;     // FFN hidden

// ---------------------------------------------------------------------------
// Device scratch (zero-init .bss; no allocations anywhere)
// ---------------------------------------------------------------------------
__device__ float g_q  [(size_t)NN * DD];
__device__ float g_k  [(size_t)NN * DD];
__device__ float g_v  [(size_t)NN * DD];
__device__ float g_sexp[(size_t)EE * HH];
__device__ float g_ssum[(size_t)NN * HH];
__device__ float g_ft2 [(size_t)NN * DD];
__device__ float g_rst [(size_t)NN * DD];
__device__ float g_h1  [(size_t)NN * D4];
__device__ float g_ffn [(size_t)NN * DD];

// ---------------------------------------------------------------------------
__global__ void zero_kernel(float* __restrict__ a, int na,
                            float* __restrict__ b, int nb)
{
    int stride = gridDim.x * blockDim.x;
    for (int j = blockIdx.x * blockDim.x + threadIdx.x; j < na; j += stride) a[j] = 0.f;
    for (int j = blockIdx.x * blockDim.x + threadIdx.x; j < nb; j += stride) b[j] = 0.f;
}

// ---------------------------------------------------------------------------
// TF32 tensor-core GEMM: C[M,N] = A[M,K] @ B[K,N] (+bias)(+PReLU)
// Block tile 128x64, BK=16, 256 threads = 8 warps in 4(m) x 2(n), warp 32x32.
// Shared layout is k-PERMUTED (within each 8-chunk: [0,4,1,5,2,6,3,7]) so
// each mma fragment is one LDS.64. A and B share the permutation, so the
// contraction result is unchanged (sum over k is order-invariant).
// mma.m16n8k8 tf32 fragments (g = lane>>2, c = lane&3):
//   A: a0=(g,c) a1=(g+8,c) a2=(g,c+4) a3=(g+8,c+4)
//   B: b0=(c,col_g) b1=(c+4,col_g)
//   C: c0=(g,2c) c1=(g,2c+1) c2=(g+8,2c) c3=(g+8,2c+1)
// MODE: 0 = plain, 1 = +bias, 2 = +bias then per-channel PReLU
// ---------------------------------------------------------------------------
__device__ __forceinline__ uint32_t f2tf32(float x) {
    uint32_t u;
    asm("cvt.rna.tf32.f32 %0, %1;" : "=r"(u) : "f"(x));
    return u;
}

__device__ __forceinline__ void mma_tf32(float* d, const uint32_t* a, const uint32_t* b) {
    asm volatile(
        "mma.sync.aligned.m16n8k8.row.col.f32.tf32.tf32.f32 "
        "{%0,%1,%2,%3}, {%4,%5,%6,%7}, {%8,%9}, {%0,%1,%2,%3};"
        : "+f"(d[0]), "+f"(d[1]), "+f"(d[2]), "+f"(d[3])
        : "r"(a[0]), "r"(a[1]), "r"(a[2]), "r"(a[3]), "r"(b[0]), "r"(b[1]));
}

template <int MODE>
__global__ void __launch_bounds__(256)
gemm_tf32(const float* __restrict__ A, const float* __restrict__ B,
          const float* __restrict__ bias, const float* __restrict__ pw,
          float* __restrict__ C, int M, int N, int K)
{
    constexpr int SK = 18;                 // padded k stride in smem
    __shared__ uint32_t As[128][SK];
    __shared__ uint32_t Bs[64][SK];

    const int tid  = threadIdx.x;
    const int lane = tid & 31;
    const int warp = tid >> 5;
    const int wm   = warp >> 1;            // 0..3
    const int wn   = warp & 1;             // 0..1
    const int g    = lane >> 2;            // 0..7
    const int c    = lane & 3;             // 0..3

    const int m0 = blockIdx.y * 128;
    const int n0 = blockIdx.x * 64;

    // A staging: thread loads float4 at rows (tid>>2, tid>>2 + 64), cols (tid&3)*4
    const int ar  = tid >> 2;              // 0..63
    const int akq = tid & 3;               // k quad 0..3
    // permuted base col for this quad: quads {0,1,2,3} -> bases {0,1,8,9}, step 2
    const int abase = (akq & 1) + ((akq >> 1) << 3);
    // B staging: thread loads float4 at row tid>>4 (k), cols (tid&15)*4
    const int bkr = tid >> 4;              // 0..15
    const int bnc = (tid & 15) * 4;
    const int bperm = ((bkr >> 3) << 3) + 2 * (bkr & 3) + ((bkr >> 2) & 1);

    float acc[2][4][4];
#pragma unroll
    for (int i = 0; i < 2; i++)
#pragma unroll
        for (int j = 0; j < 4; j++)
#pragma unroll
            for (int r = 0; r < 4; r++) acc[i][j][r] = 0.f;

    const float4 zf4 = make_float4(0.f, 0.f, 0.f, 0.f);

    for (int k0 = 0; k0 < K; k0 += 16) {
        // ---- stage A (128 x 16), tf32-converted, k-permuted ----
#pragma unroll
        for (int half = 0; half < 2; half++) {
            const int row = m0 + ar + half * 64;
            float4 av = (row < M) ? *(const float4*)(A + (size_t)row * K + k0 + akq * 4) : zf4;
            uint32_t* dstp = &As[ar + half * 64][abase];
            dstp[0] = f2tf32(av.x);
            dstp[2] = f2tf32(av.y);
            dstp[4] = f2tf32(av.z);
            dstp[6] = f2tf32(av.w);
        }
        // ---- stage B (16 x 64) transposed to [n][k_perm] ----
        {
            float4 bv = *(const float4*)(B + (size_t)(k0 + bkr) * N + n0 + bnc);
            Bs[bnc + 0][bperm] = f2tf32(bv.x);
            Bs[bnc + 1][bperm] = f2tf32(bv.y);
            Bs[bnc + 2][bperm] = f2tf32(bv.z);
            Bs[bnc + 3][bperm] = f2tf32(bv.w);
        }
        __syncthreads();

#pragma unroll
        for (int chunk = 0; chunk < 2; chunk++) {
            const int kc = chunk * 8 + 2 * c;
            uint32_t afr[2][4];
#pragma unroll
            for (int mt = 0; mt < 2; mt++) {
                const int rb = wm * 32 + mt * 16;
                uint2 x = *(const uint2*)&As[rb + g][kc];
                uint2 y = *(const uint2*)&As[rb + g + 8][kc];
                afr[mt][0] = x.x; afr[mt][1] = y.x; afr[mt][2] = x.y; afr[mt][3] = y.y;
            }
            uint32_t bfr[4][2];
#pragma unroll
            for (int nt = 0; nt < 4; nt++) {
                uint2 b2 = *(const uint2*)&Bs[wn * 32 + nt * 8 + g][kc];
                bfr[nt][0] = b2.x; bfr[nt][1] = b2.y;
            }
#pragma unroll
            for (int mt = 0; mt < 2; mt++)
#pragma unroll
                for (int nt = 0; nt < 4; nt++)
                    mma_tf32(acc[mt][nt], afr[mt], bfr[nt]);
        }
        __syncthreads();
    }

    // ---- epilogue ----
#pragma unroll
    for (int mt = 0; mt < 2; mt++) {
        const int row0 = m0 + wm * 32 + mt * 16 + g;
#pragma unroll
        for (int nt = 0; nt < 4; nt++) {
            const int col = n0 + wn * 32 + nt * 8 + 2 * c;
            float v0 = acc[mt][nt][0], v1 = acc[mt][nt][1];
            float v2 = acc[mt][nt][2], v3 = acc[mt][nt][3];
            if (MODE >= 1) {
                const float bb0 = bias[col], bb1 = bias[col + 1];
                v0 += bb0; v1 += bb1; v2 += bb0; v3 += bb1;
            }
            if (MODE == 2) {
                const float p0 = pw[col], p1 = pw[col + 1];
                v0 = (v0 >= 0.f) ? v0 : p0 * v0;
                v1 = (v1 >= 0.f) ? v1 : p1 * v1;
                v2 = (v2 >= 0.f) ? v2 : p0 * v2;
                v3 = (v3 >= 0.f) ? v3 : p1 * v3;
            }
            if (row0 < M)     *(float2*)(C + (size_t)row0 * N + col)       = make_float2(v0, v1);
            if (row0 + 8 < M) *(float2*)(C + (size_t)(row0 + 8) * N + col) = make_float2(v2, v3);
        }
    }
}

// ---------------------------------------------------------------------------
// Edge pass 1: scores -> exp -> store + segment-sum(dst). One warp per edge.
// Softmax max-shift omitted: |scores| < ~0.15, shifted/unshifted identical
// after normalization.
// ---------------------------------------------------------------------------
__global__ void edge_score_kernel(const float* __restrict__ q,
                                  const float* __restrict__ k,
                                  const int* __restrict__ src,
                                  const int* __restrict__ dst,
                                  float* __restrict__ sexp,
                                  float* __restrict__ ssum)
{
    const int e = (int)((blockIdx.x * blockDim.x + threadIdx.x) >> 5);
    const int lane = threadIdx.x & 31;
    if (e >= EE) return;
    const int s = __ldg(src + e);
    const int d = __ldg(dst + e);

    float4 kv = *(const float4*)(k + (size_t)s * DD + lane * 4);
    float4 qv = *(const float4*)(q + (size_t)d * DD + lane * 4);
    float dot = kv.x * qv.x + kv.y * qv.y + kv.z * qv.z + kv.w * qv.w;
    dot += __shfl_xor_sync(0xffffffffu, dot, 1);
    dot += __shfl_xor_sync(0xffffffffu, dot, 2);

    if ((lane & 3) == 0) {
        const int h = lane >> 2;
        float ex = __expf(dot * 0.08838834764831845f);  // 1/sqrt(128)
        sexp[(size_t)e * HH + h] = ex;
        atomicAdd(&ssum[(size_t)d * HH + h], ex);
    }
}

// ---------------------------------------------------------------------------
// Edge pass 2: a = sexp/ssum[dst]; ft2[dst] += a * v[src]  (vector red)
// ---------------------------------------------------------------------------
__global__ void edge_aggr_kernel(const float* __restrict__ v,
                                 const int* __restrict__ src,
                                 const int* __restrict__ dst,
                                 const float* __restrict__ sexp,
                                 const float* __restrict__ ssum,
                                 float* __restrict__ ft2)
{
    const int e = (int)((blockIdx.x * blockDim.x + threadIdx.x) >> 5);
    const int lane = threadIdx.x & 31;
    if (e >= EE) return;
    const int s = __ldg(src + e);
    const int d = __ldg(dst + e);
    const int h = lane >> 2;

    const float a = __ldg(sexp + (size_t)e * HH + h) / __ldg(ssum + (size_t)d * HH + h);
    float4 vv = *(const float4*)(v + (size_t)s * DD + lane * 4);
    float* out = ft2 + (size_t)d * DD + lane * 4;
    asm volatile("red.global.add.v4.f32 [%0], {%1,%2,%3,%4};"
                 :: "l"(out), "f"(vv.x * a), "f"(vv.y * a), "f"(vv.z * a), "f"(vv.w * a)
                 : "memory");
}

// ---------------------------------------------------------------------------
// LayerNorm(X + Y) * g + b; one warp per 128-float row
// ---------------------------------------------------------------------------
__global__ void ln_add_kernel(const float* __restrict__ X,
                              const float* __restrict__ Y,
                              const float* __restrict__ g,
                              const float* __restrict__ b,
                              float* __restrict__ out)
{
    const int row = (int)((blockIdx.x * blockDim.x + threadIdx.x) >> 5);
    const int lane = threadIdx.x & 31;
    if (row >= NN) return;

    float4 x = *(const float4*)(X + (size_t)row * DD + lane * 4);
    float4 y = *(const float4*)(Y + (size_t)row * DD + lane * 4);
    x.x += y.x; x.y += y.y; x.z += y.z; x.w += y.w;

    float s  = x.x + x.y + x.z + x.w;
    float ss = x.x * x.x + x.y * x.y + x.z * x.z + x.w * x.w;
#pragma unroll
    for (int o = 16; o > 0; o >>= 1) {
        s  += __shfl_xor_sync(0xffffffffu, s,  o);
        ss += __shfl_xor_sync(0xffffffffu, ss, o);
    }
    const float mu  = s * (1.f / DD);
    const float var = ss * (1.f / DD) - mu * mu;
    const float rs  = rsqrtf(var + 1e-5f);

    float4 gv = *(const float4*)(g + lane * 4);
    float4 bv = *(const float4*)(b + lane * 4);
    float4 o4;
    o4.x = (x.x - mu) * rs * gv.x + bv.x;
    o4.y = (x.y - mu) * rs * gv.y + bv.y;
    o4.z = (x.z - mu) * rs * gv.z + bv.z;
    o4.w = (x.w - mu) * rs * gv.w + bv.w;
    *(float4*)(out + (size_t)row * DD + lane * 4) = o4;
}

// ---------------------------------------------------------------------------
extern "C" void kernel_launch(void* const* d_in, const int* in_sizes, int n_in,
                              void* d_out, int out_size)
{
    const float* feat  = (const float*)d_in[0];
    const int*   src   = (const int*)  d_in[1];
    const int*   dst   = (const int*)  d_in[2];
    const float* Wq    = (const float*)d_in[3];
    const float* Wk    = (const float*)d_in[4];
    const float* Wv    = (const float*)d_in[5];
    const float* ln1_g = (const float*)d_in[6];
    const float* ln1_b = (const float*)d_in[7];
    const float* ln2_g = (const float*)d_in[8];
    const float* ln2_b = (const float*)d_in[9];
    const float* W1    = (const float*)d_in[10];
    const float* b1    = (const float*)d_in[11];
    const float* pw    = (const float*)d_in[12];
    const float* W2    = (const float*)d_in[13];
    const float* b2    = (const float*)d_in[14];
    float* out = (float*)d_out;

    float *q, *k, *v, *sexp, *ssum, *ft2, *rst, *h1, *ffn;
    cudaGetSymbolAddress((void**)&q,    g_q);
    cudaGetSymbolAddress((void**)&k,    g_k);
    cudaGetSymbolAddress((void**)&v,    g_v);
    cudaGetSymbolAddress((void**)&sexp, g_sexp);
    cudaGetSymbolAddress((void**)&ssum, g_ssum);
    cudaGetSymbolAddress((void**)&ft2,  g_ft2);
    cudaGetSymbolAddress((void**)&rst,  g_rst);
    cudaGetSymbolAddress((void**)&h1,   g_h1);
    cudaGetSymbolAddress((void**)&ffn,  g_ffn);

    // 1) zero atomic accumulators (every call: graph replays reuse scratch)
    zero_kernel<<<2048, 256>>>(ssum, NN * HH, ft2, NN * DD);

    const int mblocks = (NN + 127) / 128;   // 313

    // 2) QKV projections: [40000,128] @ [128,128]
    dim3 gqkv(DD / 64, mblocks);
    gemm_tf32<0><<<gqkv, 256>>>(feat, Wq, nullptr, nullptr, q, NN, DD, DD);
    gemm_tf32<0><<<gqkv, 256>>>(feat, Wk, nullptr, nullptr, k, NN, DD, DD);
    gemm_tf32<0><<<gqkv, 256>>>(feat, Wv, nullptr, nullptr, v, NN, DD, DD);

    // 3) edge scores + segment-sum of exp
    const int edge_blocks = (EE * 32 + 255) / 256;
    edge_score_kernel<<<edge_blocks, 256>>>(q, k, src, dst, sexp, ssum);

    // 4) normalized weighted aggregation into ft2
    edge_aggr_kernel<<<edge_blocks, 256>>>(v, src, dst, sexp, ssum, ft2);

    // 5) rst = LN(ft2 + feat)
    const int ln_blocks = (NN * 32 + 255) / 256;
    ln_add_kernel<<<ln_blocks, 256>>>(ft2, feat, ln1_g, ln1_b, rst);

    // 6) FFN1: h1 = PReLU(rst @ W1 + b1)   [40000,128]@[128,512]
    gemm_tf32<2><<<dim3(D4 / 64, mblocks), 256>>>(rst, W1, b1, pw, h1, NN, D4, DD);

    // 7) FFN2: ffn = h1 @ W2 + b2          [40000,512]@[512,128]
    gemm_tf32<1><<<dim3(DD / 64, mblocks), 256>>>(h1, W2, b2, nullptr, ffn, NN, DD, D4);

    // 8) out = LN(rst + ffn)
    ln_add_kernel<<<ln_blocks, 256>>>(rst, ffn, ln2_g, ln2_b, out);
}

// round 4
// speedup vs baseline: 2.4762x; 1.5597x over previous
#include <cuda_runtime.h>
#include <cuda_bf16.h>
#include <cstdint>
#include <cstddef>

constexpr int NN = 40000;   // nodes
constexpr int EE = 640000;  // edges
constexpr int DD = 128;     // feature dim
constexpr int HH = 8;       // heads
constexpr int D4 = 512;     // FFN hidden

// ---------------------------------------------------------------------------
// Device scratch (zero-init .bss; no allocations anywhere)
// ---------------------------------------------------------------------------
__device__ float g_q  [(size_t)NN * DD];
__device__ float g_k  [(size_t)NN * DD];
__device__ float g_v  [(size_t)NN * DD];
__device__ float g_ssum[(size_t)NN * HH];
__device__ float g_ft2 [(size_t)NN * DD];
__device__ float g_rst [(size_t)NN * DD];
__device__ float g_h1  [(size_t)NN * D4];
__device__ float g_ffn [(size_t)NN * DD];

// ---------------------------------------------------------------------------
__global__ void zero_kernel(float* __restrict__ a, int na,
                            float* __restrict__ b, int nb)
{
    int stride = gridDim.x * blockDim.x;
    for (int j = blockIdx.x * blockDim.x + threadIdx.x; j < na; j += stride) a[j] = 0.f;
    for (int j = blockIdx.x * blockDim.x + threadIdx.x; j < nb; j += stride) b[j] = 0.f;
}

// ---------------------------------------------------------------------------
// TF32 tensor-core GEMM, cp.async double-buffered.
// C[M,N] = A[M,K] @ B[K,N] (+bias)(+PReLU)
// Block tile 128x64, BK=16, 256 threads = 8 warps (4m x 2n), warp tile 32x32.
// Smem: natural layouts, A pad to 20 floats/row, B pad to 72 floats/row --
// both conflict-free for the m16n8k8 fragment pattern and 16B-aligned for
// cp.async. fp32 staged raw; cvt.rna.tf32 applied on register fragments.
// MODE: 0 = plain, 1 = +bias, 2 = +bias then per-channel PReLU
// ---------------------------------------------------------------------------
__device__ __forceinline__ uint32_t f2tf32(float x) {
    uint32_t u;
    asm("cvt.rna.tf32.f32 %0, %1;" : "=r"(u) : "f"(x));
    return u;
}

__device__ __forceinline__ void mma_tf32(float* d, const uint32_t* a, const uint32_t* b) {
    asm volatile(
        "mma.sync.aligned.m16n8k8.row.col.f32.tf32.tf32.f32 "
        "{%0,%1,%2,%3}, {%4,%5,%6,%7}, {%8,%9}, {%0,%1,%2,%3};"
        : "+f"(d[0]), "+f"(d[1]), "+f"(d[2]), "+f"(d[3])
        : "r"(a[0]), "r"(a[1]), "r"(a[2]), "r"(a[3]), "r"(b[0]), "r"(b[1]));
}

__device__ __forceinline__ void cp_async16(void* smem_dst, const void* gmem_src, int src_bytes) {
    uint32_t d = (uint32_t)__cvta_generic_to_shared(smem_dst);
    asm volatile("cp.async.ca.shared.global [%0], [%1], 16, %2;"
                 :: "r"(d), "l"(gmem_src), "r"(src_bytes));
}

template <int MODE>
__global__ void __launch_bounds__(256)
gemm_tf32(const float* __restrict__ A, const float* __restrict__ B,
          const float* __restrict__ bias, const float* __restrict__ pw,
          float* __restrict__ C, int M, int N, int K)
{
    __shared__ float As[2][128][20];
    __shared__ float Bs[2][16][72];

    const int tid  = threadIdx.x;
    const int lane = tid & 31;
    const int warp = tid >> 5;
    const int wm   = warp >> 1;            // 0..3
    const int wn   = warp & 1;             // 0..1
    const int g    = lane >> 2;            // 0..7
    const int c    = lane & 3;             // 0..3

    const int m0 = blockIdx.y * 128;
    const int n0 = blockIdx.x * 64;

    // A stage: thread covers rows {ar, ar+64}, k-quad akq (4 floats)
    const int ar  = tid >> 2;              // 0..63
    const int akq = tid & 3;               // 0..3
    // B stage: thread covers k-row bkr, n cols [bnc, bnc+4)
    const int bkr = tid >> 4;              // 0..15
    const int bnc = (tid & 15) * 4;

    float acc[2][4][4];
#pragma unroll
    for (int i = 0; i < 2; i++)
#pragma unroll
        for (int j = 0; j < 4; j++)
#pragma unroll
            for (int r = 0; r < 4; r++) acc[i][j][r] = 0.f;

    auto load_tile = [&](int buf, int k0) {
#pragma unroll
        for (int half = 0; half < 2; half++) {
            const int row = m0 + ar + half * 64;
            cp_async16(&As[buf][ar + half * 64][akq * 4],
                       A + (size_t)row * K + k0 + akq * 4,
                       (row < M) ? 16 : 0);
        }
        cp_async16(&Bs[buf][bkr][bnc],
                   B + (size_t)(k0 + bkr) * N + n0 + bnc, 16);
        asm volatile("cp.async.commit_group;" ::: "memory");
    };

    const int nk = K >> 4;
    load_tile(0, 0);

    for (int i = 0; i < nk; i++) {
        if (i + 1 < nk) {
            load_tile((i + 1) & 1, (i + 1) << 4);
            asm volatile("cp.async.wait_group 1;" ::: "memory");
        } else {
            asm volatile("cp.async.wait_group 0;" ::: "memory");
        }
        __syncthreads();

        const int buf = i & 1;
#pragma unroll
        for (int chunk = 0; chunk < 2; chunk++) {
            const int kc = chunk * 8;
            uint32_t afr[2][4];
#pragma unroll
            for (int mt = 0; mt < 2; mt++) {
                const int rb = wm * 32 + mt * 16;
                afr[mt][0] = f2tf32(As[buf][rb + g][kc + c]);
                afr[mt][1] = f2tf32(As[buf][rb + g + 8][kc + c]);
                afr[mt][2] = f2tf32(As[buf][rb + g][kc + c + 4]);
                afr[mt][3] = f2tf32(As[buf][rb + g + 8][kc + c + 4]);
            }
            uint32_t bfr[4][2];
#pragma unroll
            for (int nt = 0; nt < 4; nt++) {
                const int nb = wn * 32 + nt * 8 + g;
                bfr[nt][0] = f2tf32(Bs[buf][kc + c][nb]);
                bfr[nt][1] = f2tf32(Bs[buf][kc + c + 4][nb]);
            }
#pragma unroll
            for (int mt = 0; mt < 2; mt++)
#pragma unroll
                for (int nt = 0; nt < 4; nt++)
                    mma_tf32(acc[mt][nt], afr[mt], bfr[nt]);
        }
        __syncthreads();
    }

    // ---- epilogue ----
#pragma unroll
    for (int mt = 0; mt < 2; mt++) {
        const int row0 = m0 + wm * 32 + mt * 16 + g;
#pragma unroll
        for (int nt = 0; nt < 4; nt++) {
            const int col = n0 + wn * 32 + nt * 8 + 2 * c;
            float v0 = acc[mt][nt][0], v1 = acc[mt][nt][1];
            float v2 = acc[mt][nt][2], v3 = acc[mt][nt][3];
            if (MODE >= 1) {
                const float bb0 = bias[col], bb1 = bias[col + 1];
                v0 += bb0; v1 += bb1; v2 += bb0; v3 += bb1;
            }
            if (MODE == 2) {
                const float p0 = pw[col], p1 = pw[col + 1];
                v0 = (v0 >= 0.f) ? v0 : p0 * v0;
                v1 = (v1 >= 0.f) ? v1 : p1 * v1;
                v2 = (v2 >= 0.f) ? v2 : p0 * v2;
                v3 = (v3 >= 0.f) ? v3 : p1 * v3;
            }
            if (row0 < M)     *(float2*)(C + (size_t)row0 * N + col)       = make_float2(v0, v1);
            if (row0 + 8 < M) *(float2*)(C + (size_t)(row0 + 8) * N + col) = make_float2(v2, v3);
        }
    }
}

// ---------------------------------------------------------------------------
// FUSED edge pass: score -> exp -> {ssum[dst] += ex, ft2[dst] += ex * v[src]}
// Normalization by ssum is deferred to the LN1 kernel (it commutes with the
// segment sum). One warp per edge; softmax max-shift omitted (|scores|<~0.15,
// mathematically identical after normalization).
// ---------------------------------------------------------------------------
__global__ void edge_fused_kernel(const float* __restrict__ q,
                                  const float* __restrict__ k,
                                  const float* __restrict__ v,
                                  const int* __restrict__ src,
                                  const int* __restrict__ dst,
                                  float* __restrict__ ssum,
                                  float* __restrict__ ft2)
{
    const int e = (int)((blockIdx.x * blockDim.x + threadIdx.x) >> 5);
    const int lane = threadIdx.x & 31;
    if (e >= EE) return;
    const int s = __ldg(src + e);
    const int d = __ldg(dst + e);

    float4 kv = *(const float4*)(k + (size_t)s * DD + lane * 4);
    float4 qv = *(const float4*)(q + (size_t)d * DD + lane * 4);
    float dot = kv.x * qv.x + kv.y * qv.y + kv.z * qv.z + kv.w * qv.w;
    dot += __shfl_xor_sync(0xffffffffu, dot, 1);
    dot += __shfl_xor_sync(0xffffffffu, dot, 2);
    // all 4 lanes of each head-quad now hold the head's dot
    const float ex = __expf(dot * 0.08838834764831845f);  // 1/sqrt(128)

    if ((lane & 3) == 0)
        atomicAdd(&ssum[(size_t)d * HH + (lane >> 2)], ex);

    float4 vv = *(const float4*)(v + (size_t)s * DD + lane * 4);
    float* outp = ft2 + (size_t)d * DD + lane * 4;
    asm volatile("red.global.add.v4.f32 [%0], {%1,%2,%3,%4};"
                 :: "l"(outp), "f"(vv.x * ex), "f"(vv.y * ex), "f"(vv.z * ex), "f"(vv.w * ex)
                 : "memory");
}

// ---------------------------------------------------------------------------
// rst = LN(ft2/ssum[dst,h] + feat) * g + b; one warp per 128-float row
// ---------------------------------------------------------------------------
__global__ void ln_div_add_kernel(const float* __restrict__ X,
                                  const float* __restrict__ ssum,
                                  const float* __restrict__ Y,
                                  const float* __restrict__ g,
                                  const float* __restrict__ b,
                                  float* __restrict__ out)
{
    const int row = (int)((blockIdx.x * blockDim.x + threadIdx.x) >> 5);
    const int lane = threadIdx.x & 31;
    if (row >= NN) return;

    const float inv = 1.f / __ldg(ssum + (size_t)row * HH + (lane >> 2));
    float4 x = *(const float4*)(X + (size_t)row * DD + lane * 4);
    float4 y = *(const float4*)(Y + (size_t)row * DD + lane * 4);
    x.x = x.x * inv + y.x; x.y = x.y * inv + y.y;
    x.z = x.z * inv + y.z; x.w = x.w * inv + y.w;

    float s  = x.x + x.y + x.z + x.w;
    float ss = x.x * x.x + x.y * x.y + x.z * x.z + x.w * x.w;
#pragma unroll
    for (int o = 16; o > 0; o >>= 1) {
        s  += __shfl_xor_sync(0xffffffffu, s,  o);
        ss += __shfl_xor_sync(0xffffffffu, ss, o);
    }
    const float mu  = s * (1.f / DD);
    const float var = ss * (1.f / DD) - mu * mu;
    const float rs  = rsqrtf(var + 1e-5f);

    float4 gv = *(const float4*)(g + lane * 4);
    float4 bv = *(const float4*)(b + lane * 4);
    float4 o4;
    o4.x = (x.x - mu) * rs * gv.x + bv.x;
    o4.y = (x.y - mu) * rs * gv.y + bv.y;
    o4.z = (x.z - mu) * rs * gv.z + bv.z;
    o4.w = (x.w - mu) * rs * gv.w + bv.w;
    *(float4*)(out + (size_t)row * DD + lane * 4) = o4;
}

// ---------------------------------------------------------------------------
// out = LN(X + Y) * g + b
// ---------------------------------------------------------------------------
__global__ void ln_add_kernel(const float* __restrict__ X,
                              const float* __restrict__ Y,
                              const float* __restrict__ g,
                              const float* __restrict__ b,
                              float* __restrict__ out)
{
    const int row = (int)((blockIdx.x * blockDim.x + threadIdx.x) >> 5);
    const int lane = threadIdx.x & 31;
    if (row >= NN) return;

    float4 x = *(const float4*)(X + (size_t)row * DD + lane * 4);
    float4 y = *(const float4*)(Y + (size_t)row * DD + lane * 4);
    x.x += y.x; x.y += y.y; x.z += y.z; x.w += y.w;

    float s  = x.x + x.y + x.z + x.w;
    float ss = x.x * x.x + x.y * x.y + x.z * x.z + x.w * x.w;
#pragma unroll
    for (int o = 16; o > 0; o >>= 1) {
        s  += __shfl_xor_sync(0xffffffffu, s,  o);
        ss += __shfl_xor_sync(0xffffffffu, ss, o);
    }
    const float mu  = s * (1.f / DD);
    const float var = ss * (1.f / DD) - mu * mu;
    const float rs  = rsqrtf(var + 1e-5f);

    float4 gv = *(const float4*)(g + lane * 4);
    float4 bv = *(const float4*)(b + lane * 4);
    float4 o4;
    o4.x = (x.x - mu) * rs * gv.x + bv.x;
    o4.y = (x.y - mu) * rs * gv.y + bv.y;
    o4.z = (x.z - mu) * rs * gv.z + bv.z;
    o4.w = (x.w - mu) * rs * gv.w + bv.w;
    *(float4*)(out + (size_t)row * DD + lane * 4) = o4;
}

// ---------------------------------------------------------------------------
extern "C" void kernel_launch(void* const* d_in, const int* in_sizes, int n_in,
                              void* d_out, int out_size)
{
    const float* feat  = (const float*)d_in[0];
    const int*   src   = (const int*)  d_in[1];
    const int*   dst   = (const int*)  d_in[2];
    const float* Wq    = (const float*)d_in[3];
    const float* Wk    = (const float*)d_in[4];
    const float* Wv    = (const float*)d_in[5];
    const float* ln1_g = (const float*)d_in[6];
    const float* ln1_b = (const float*)d_in[7];
    const float* ln2_g = (const float*)d_in[8];
    const float* ln2_b = (const float*)d_in[9];
    const float* W1    = (const float*)d_in[10];
    const float* b1    = (const float*)d_in[11];
    const float* pw    = (const float*)d_in[12];
    const float* W2    = (const float*)d_in[13];
    const float* b2    = (const float*)d_in[14];
    float* out = (float*)d_out;

    float *q, *k, *v, *ssum, *ft2, *rst, *h1, *ffn;
    cudaGetSymbolAddress((void**)&q,    g_q);
    cudaGetSymbolAddress((void**)&k,    g_k);
    cudaGetSymbolAddress((void**)&v,    g_v);
    cudaGetSymbolAddress((void**)&ssum, g_ssum);
    cudaGetSymbolAddress((void**)&ft2,  g_ft2);
    cudaGetSymbolAddress((void**)&rst,  g_rst);
    cudaGetSymbolAddress((void**)&h1,   g_h1);
    cudaGetSymbolAddress((void**)&ffn,  g_ffn);

    // 1) zero atomic accumulators (every call: graph replays reuse scratch)
    zero_kernel<<<2048, 256>>>(ssum, NN * HH, ft2, NN * DD);

    const int mblocks = (NN + 127) / 128;   // 313

    // 2) QKV projections: [40000,128] @ [128,128]
    dim3 gqkv(DD / 64, mblocks);
    gemm_tf32<0><<<gqkv, 256>>>(feat, Wq, nullptr, nullptr, q, NN, DD, DD);
    gemm_tf32<0><<<gqkv, 256>>>(feat, Wk, nullptr, nullptr, k, NN, DD, DD);
    gemm_tf32<0><<<gqkv, 256>>>(feat, Wv, nullptr, nullptr, v, NN, DD, DD);

    // 3) fused edge pass: ssum += exp(s); ft2 += exp(s) * v[src]
    const int edge_blocks = (EE * 32 + 255) / 256;
    edge_fused_kernel<<<edge_blocks, 256>>>(q, k, v, src, dst, ssum, ft2);

    // 4) rst = LN(ft2/ssum + feat)
    const int ln_blocks = (NN * 32 + 255) / 256;
    ln_div_add_kernel<<<ln_blocks, 256>>>(ft2, ssum, feat, ln1_g, ln1_b, rst);

    // 5) FFN1: h1 = PReLU(rst @ W1 + b1)   [40000,128]@[128,512]
    gemm_tf32<2><<<dim3(D4 / 64, mblocks), 256>>>(rst, W1, b1, pw, h1, NN, D4, DD);

    // 6) FFN2: ffn = h1 @ W2 + b2          [40000,512]@[512,128]
    gemm_tf32<1><<<dim3(DD / 64, mblocks), 256>>>(h1, W2, b2, nullptr, ffn, NN, DD, D4);

    // 7) out = LN(rst + ffn)
    ln_add_kernel<<<ln_blocks, 256>>>(rst, ffn, ln2_g, ln2_b, out);
}

// round 5
// speedup vs baseline: 3.2284x; 1.3038x over previous
#include <cuda_runtime.h>
#include <cuda_bf16.h>
#include <cstdint>
#include <cstddef>

constexpr int NN = 40000;   // nodes
constexpr int EE = 640000;  // edges
constexpr int DD = 128;     // feature dim
constexpr int HH = 8;       // heads
constexpr int D4 = 512;     // FFN hidden

// ---------------------------------------------------------------------------
// Device scratch (zero-init .bss; no allocations anywhere)
// ---------------------------------------------------------------------------
__device__ __nv_bfloat16 g_featb[(size_t)NN * DD];
__device__ __nv_bfloat16 g_wqb [(size_t)DD * DD];
__device__ __nv_bfloat16 g_wkb [(size_t)DD * DD];
__device__ __nv_bfloat16 g_wvb [(size_t)DD * DD];
__device__ __nv_bfloat16 g_w1b [(size_t)DD * D4];
__device__ __nv_bfloat16 g_w2b [(size_t)D4 * DD];
__device__ __nv_bfloat16 g_qb  [(size_t)NN * DD];
__device__ __nv_bfloat16 g_kb  [(size_t)NN * DD];
__device__ __nv_bfloat16 g_vb  [(size_t)NN * DD];
__device__ __nv_bfloat16 g_rstb[(size_t)NN * DD];
__device__ __nv_bfloat16 g_h1b [(size_t)NN * D4];
__device__ float g_ssum[(size_t)NN * HH];
__device__ float g_ft2 [(size_t)NN * DD];
__device__ float g_rst [(size_t)NN * DD];
__device__ float g_ffn [(size_t)NN * DD];

// ---------------------------------------------------------------------------
__global__ void zero_kernel(float* __restrict__ a, int na,
                            float* __restrict__ b, int nb)
{
    int stride = gridDim.x * blockDim.x;
    for (int j = blockIdx.x * blockDim.x + threadIdx.x; j < na; j += stride) a[j] = 0.f;
    for (int j = blockIdx.x * blockDim.x + threadIdx.x; j < nb; j += stride) b[j] = 0.f;
}

// f32 -> bf16, 4 elems/thread (n % 4 == 0 for all uses)
__global__ void cvt_bf16_kernel(const float* __restrict__ in,
                                __nv_bfloat16* __restrict__ out, int n4)
{
    int i = blockIdx.x * blockDim.x + threadIdx.x;
    if (i >= n4) return;
    float4 x = *(const float4*)(in + (size_t)i * 4);
    __nv_bfloat162 p0 = __floats2bfloat162_rn(x.x, x.y);
    __nv_bfloat162 p1 = __floats2bfloat162_rn(x.z, x.w);
    uint2 pk;
    pk.x = *(uint32_t*)&p0;
    pk.y = *(uint32_t*)&p1;
    *(uint2*)(out + (size_t)i * 4) = pk;
}

// ---------------------------------------------------------------------------
// BF16 tensor-core GEMM: C[M,N] = A[M,K] @ B[K,N] (+bias)(+PReLU)
// A,B bf16 row-major; accum fp32. Block tile 128x64, BK=32, 3-stage cp.async
// ring, 1 barrier/iter. 256 thr = 8 warps (4m x 2n), warp tile 32x32.
// Fragments via ldmatrix.x4 (A) and ldmatrix.x4.trans (B).
// Smem strides: A 40 bf16 (80B -> 20r%32 banks distinct), B 72 bf16 (144B ->
// 4r%32 distinct) — conflict-free for ldmatrix, 16B-aligned for cp.async.
// MODE: 0 plain, 1 +bias, 2 +bias+PReLU.  OUTBF: store bf16 instead of f32.
// ---------------------------------------------------------------------------
__device__ __forceinline__ void mma_bf16(float* d, const uint32_t* a, const uint32_t* b) {
    asm volatile(
        "mma.sync.aligned.m16n8k16.row.col.f32.bf16.bf16.f32 "
        "{%0,%1,%2,%3}, {%4,%5,%6,%7}, {%8,%9}, {%0,%1,%2,%3};"
        : "+f"(d[0]), "+f"(d[1]), "+f"(d[2]), "+f"(d[3])
        : "r"(a[0]), "r"(a[1]), "r"(a[2]), "r"(a[3]), "r"(b[0]), "r"(b[1]));
}

__device__ __forceinline__ void ldsm_x4(uint32_t* r, const void* p) {
    uint32_t a = (uint32_t)__cvta_generic_to_shared(p);
    asm volatile("ldmatrix.sync.aligned.m8n8.x4.shared.b16 {%0,%1,%2,%3}, [%4];"
                 : "=r"(r[0]), "=r"(r[1]), "=r"(r[2]), "=r"(r[3]) : "r"(a));
}

__device__ __forceinline__ void ldsm_x4_t(uint32_t* r, const void* p) {
    uint32_t a = (uint32_t)__cvta_generic_to_shared(p);
    asm volatile("ldmatrix.sync.aligned.m8n8.x4.trans.shared.b16 {%0,%1,%2,%3}, [%4];"
                 : "=r"(r[0]), "=r"(r[1]), "=r"(r[2]), "=r"(r[3]) : "r"(a));
}

__device__ __forceinline__ void cp_async16(void* smem_dst, const void* gmem_src, int src_bytes) {
    uint32_t d = (uint32_t)__cvta_generic_to_shared(smem_dst);
    asm volatile("cp.async.ca.shared.global [%0], [%1], 16, %2;"
                 :: "r"(d), "l"(gmem_src), "r"(src_bytes));
}

template <int MODE, bool OUTBF>
__global__ void __launch_bounds__(256)
gemm_bf16(const __nv_bfloat16* __restrict__ A, const __nv_bfloat16* __restrict__ B,
          const float* __restrict__ bias, const float* __restrict__ pw,
          void* __restrict__ Cv, int M, int N, int K)
{
    constexpr int BK = 32;
    constexpr int ST = 3;
    __shared__ __nv_bfloat16 As[ST][128][BK + 8];   // stride 40 elems
    __shared__ __nv_bfloat16 Bs[ST][BK][64 + 8];    // stride 72 elems

    const int tid  = threadIdx.x;
    const int lane = tid & 31;
    const int warp = tid >> 5;
    const int wm   = warp >> 1;            // 0..3
    const int wn   = warp & 1;             // 0..1
    const int g    = lane >> 2;
    const int c    = lane & 3;

    const int m0 = blockIdx.y * 128;
    const int n0 = blockIdx.x * 64;

    float acc[2][4][4];
#pragma unroll
    for (int i = 0; i < 2; i++)
#pragma unroll
        for (int j = 0; j < 4; j++)
#pragma unroll
            for (int r = 0; r < 4; r++) acc[i][j][r] = 0.f;

    auto load_tile = [&](int buf, int k0) {
        // A: 128 rows x 32 k = 512 x 16B chunks; 2 per thread
#pragma unroll
        for (int j = 0; j < 2; j++) {
            const int idx = tid + 256 * j;
            const int row = idx >> 2;
            const int kc8 = (idx & 3) * 8;
            cp_async16(&As[buf][row][kc8],
                       A + (size_t)(m0 + row) * K + k0 + kc8,
                       (m0 + row < M) ? 16 : 0);
        }
        // B: 32 rows x 64 n = 256 x 16B chunks; 1 per thread
        {
            const int row = tid >> 3;
            const int nc8 = (tid & 7) * 8;
            cp_async16(&Bs[buf][row][nc8],
                       B + (size_t)(k0 + row) * N + n0 + nc8, 16);
        }
        asm volatile("cp.async.commit_group;" ::: "memory");
    };

    const int nk = K / BK;                 // 4 or 16 (always >= 2)
    load_tile(0, 0);
    load_tile(1, BK);

    // fragment smem coords (constant across iters)
    const int a_r = lane & 15;
    const int a_c = (lane >> 4) << 3;
    const int b_r = (lane & 7) + (lane & 8);
    const int b_c = (lane & 16) >> 1;

    for (int i = 0; i < nk; i++) {
        if (i < nk - 1) asm volatile("cp.async.wait_group 1;" ::: "memory");
        else            asm volatile("cp.async.wait_group 0;" ::: "memory");
        __syncthreads();

        const int nx = i + 2;
        if (nx < nk) load_tile(nx % ST, nx * BK);

        const int buf = i % ST;
#pragma unroll
        for (int chunk = 0; chunk < 2; chunk++) {
            const int kc = chunk * 16;
            uint32_t afr[2][4];
#pragma unroll
            for (int mt = 0; mt < 2; mt++)
                ldsm_x4(afr[mt], &As[buf][wm * 32 + mt * 16 + a_r][kc + a_c]);
            uint32_t bfr[2][4];
#pragma unroll
            for (int ng = 0; ng < 2; ng++)
                ldsm_x4_t(bfr[ng], &Bs[buf][kc + b_r][wn * 32 + ng * 16 + b_c]);
#pragma unroll
            for (int mt = 0; mt < 2; mt++)
#pragma unroll
                for (int ng = 0; ng < 2; ng++) {
                    mma_bf16(acc[mt][ng * 2 + 0], afr[mt], &bfr[ng][0]);
                    mma_bf16(acc[mt][ng * 2 + 1], afr[mt], &bfr[ng][2]);
                }
        }
    }

    // ---- epilogue ----
#pragma unroll
    for (int mt = 0; mt < 2; mt++) {
        const int row0 = m0 + wm * 32 + mt * 16 + g;
#pragma unroll
        for (int nt = 0; nt < 4; nt++) {
            const int col = n0 + wn * 32 + nt * 8 + 2 * c;
            float v0 = acc[mt][nt][0], v1 = acc[mt][nt][1];
            float v2 = acc[mt][nt][2], v3 = acc[mt][nt][3];
            if (MODE >= 1) {
                const float bb0 = bias[col], bb1 = bias[col + 1];
                v0 += bb0; v1 += bb1; v2 += bb0; v3 += bb1;
            }
            if (MODE == 2) {
                const float p0 = pw[col], p1 = pw[col + 1];
                v0 = (v0 >= 0.f) ? v0 : p0 * v0;
                v1 = (v1 >= 0.f) ? v1 : p1 * v1;
                v2 = (v2 >= 0.f) ? v2 : p0 * v2;
                v3 = (v3 >= 0.f) ? v3 : p1 * v3;
            }
            if (OUTBF) {
                __nv_bfloat16* Cb = (__nv_bfloat16*)Cv;
                __nv_bfloat162 p01 = __floats2bfloat162_rn(v0, v1);
                __nv_bfloat162 p23 = __floats2bfloat162_rn(v2, v3);
                if (row0 < M)     *(__nv_bfloat162*)(Cb + (size_t)row0 * N + col)       = p01;
                if (row0 + 8 < M) *(__nv_bfloat162*)(Cb + (size_t)(row0 + 8) * N + col) = p23;
            } else {
                float* Cf = (float*)Cv;
                if (row0 < M)     *(float2*)(Cf + (size_t)row0 * N + col)       = make_float2(v0, v1);
                if (row0 + 8 < M) *(float2*)(Cf + (size_t)(row0 + 8) * N + col) = make_float2(v2, v3);
            }
        }
    }
}

// ---------------------------------------------------------------------------
// FUSED edge pass (bf16 q/k/v): score -> exp -> {ssum[dst]+=ex, ft2[dst]+=ex*v}
// One warp per edge; lane covers 4 elems (8B bf16). Softmax max-shift omitted
// (|scores| < ~0.15; identical after normalization).
// ---------------------------------------------------------------------------
__global__ void edge_fused_kernel(const __nv_bfloat16* __restrict__ q,
                                  const __nv_bfloat16* __restrict__ k,
                                  const __nv_bfloat16* __restrict__ v,
                                  const int* __restrict__ src,
                                  const int* __restrict__ dst,
                                  float* __restrict__ ssum,
                                  float* __restrict__ ft2)
{
    const int e = (int)((blockIdx.x * blockDim.x + threadIdx.x) >> 5);
    const int lane = threadIdx.x & 31;
    if (e >= EE) return;
    const int s = __ldg(src + e);
    const int d = __ldg(dst + e);

    uint2 kraw = ((const uint2*)(k + (size_t)s * DD))[lane];
    uint2 qraw = ((const uint2*)(q + (size_t)d * DD))[lane];
    float2 k0 = __bfloat1622float2(*(__nv_bfloat162*)&kraw.x);
    float2 k1 = __bfloat1622float2(*(__nv_bfloat162*)&kraw.y);
    float2 q0 = __bfloat1622float2(*(__nv_bfloat162*)&qraw.x);
    float2 q1 = __bfloat1622float2(*(__nv_bfloat162*)&qraw.y);
    float dot = k0.x * q0.x + k0.y * q0.y + k1.x * q1.x + k1.y * q1.y;
    dot += __shfl_xor_sync(0xffffffffu, dot, 1);
    dot += __shfl_xor_sync(0xffffffffu, dot, 2);
    const float ex = __expf(dot * 0.08838834764831845f);  // 1/sqrt(128)

    if ((lane & 3) == 0)
        atomicAdd(&ssum[(size_t)d * HH + (lane >> 2)], ex);

    uint2 vraw = ((const uint2*)(v + (size_t)s * DD))[lane];
    float2 v0 = __bfloat1622float2(*(__nv_bfloat162*)&vraw.x);
    float2 v1 = __bfloat1622float2(*(__nv_bfloat162*)&vraw.y);
    float* outp = ft2 + (size_t)d * DD + lane * 4;
    asm volatile("red.global.add.v4.f32 [%0], {%1,%2,%3,%4};"
                 :: "l"(outp), "f"(v0.x * ex), "f"(v0.y * ex), "f"(v1.x * ex), "f"(v1.y * ex)
                 : "memory");
}

// ---------------------------------------------------------------------------
// rst = LN(ft2/ssum[row,h] + feat); writes fp32 rst AND bf16 rst
// ---------------------------------------------------------------------------
__global__ void ln_div_add_kernel(const float* __restrict__ X,
                                  const float* __restrict__ ssum,
                                  const float* __restrict__ Y,
                                  const float* __restrict__ g,
                                  const float* __restrict__ b,
                                  float* __restrict__ out,
                                  __nv_bfloat16* __restrict__ outb)
{
    const int row = (int)((blockIdx.x * blockDim.x + threadIdx.x) >> 5);
    const int lane = threadIdx.x & 31;
    if (row >= NN) return;

    const float inv = 1.f / __ldg(ssum + (size_t)row * HH + (lane >> 2));
    float4 x = *(const float4*)(X + (size_t)row * DD + lane * 4);
    float4 y = *(const float4*)(Y + (size_t)row * DD + lane * 4);
    x.x = x.x * inv + y.x; x.y = x.y * inv + y.y;
    x.z = x.z * inv + y.z; x.w = x.w * inv + y.w;

    float s  = x.x + x.y + x.z + x.w;
    float ss = x.x * x.x + x.y * x.y + x.z * x.z + x.w * x.w;
#pragma unroll
    for (int o = 16; o > 0; o >>= 1) {
        s  += __shfl_xor_sync(0xffffffffu, s,  o);
        ss += __shfl_xor_sync(0xffffffffu, ss, o);
    }
    const float mu  = s * (1.f / DD);
    const float var = ss * (1.f / DD) - mu * mu;
    const float rs  = rsqrtf(var + 1e-5f);

    float4 gv = *(const float4*)(g + lane * 4);
    float4 bv = *(const float4*)(b + lane * 4);
    float4 o4;
    o4.x = (x.x - mu) * rs * gv.x + bv.x;
    o4.y = (x.y - mu) * rs * gv.y + bv.y;
    o4.z = (x.z - mu) * rs * gv.z + bv.z;
    o4.w = (x.w - mu) * rs * gv.w + bv.w;
    *(float4*)(out + (size_t)row * DD + lane * 4) = o4;

    __nv_bfloat162 p0 = __floats2bfloat162_rn(o4.x, o4.y);
    __nv_bfloat162 p1 = __floats2bfloat162_rn(o4.z, o4.w);
    uint2 pk; pk.x = *(uint32_t*)&p0; pk.y = *(uint32_t*)&p1;
    *(uint2*)(outb + (size_t)row * DD + lane * 4) = pk;
}

// ---------------------------------------------------------------------------
// out = LN(X + Y) * g + b
// ---------------------------------------------------------------------------
__global__ void ln_add_kernel(const float* __restrict__ X,
                              const float* __restrict__ Y,
                              const float* __restrict__ g,
                              const float* __restrict__ b,
                              float* __restrict__ out)
{
    const int row = (int)((blockIdx.x * blockDim.x + threadIdx.x) >> 5);
    const int lane = threadIdx.x & 31;
    if (row >= NN) return;

    float4 x = *(const float4*)(X + (size_t)row * DD + lane * 4);
    float4 y = *(const float4*)(Y + (size_t)row * DD + lane * 4);
    x.x += y.x; x.y += y.y; x.z += y.z; x.w += y.w;

    float s  = x.x + x.y + x.z + x.w;
    float ss = x.x * x.x + x.y * x.y + x.z * x.z + x.w * x.w;
#pragma unroll
    for (int o = 16; o > 0; o >>= 1) {
        s  += __shfl_xor_sync(0xffffffffu, s,  o);
        ss += __shfl_xor_sync(0xffffffffu, ss, o);
    }
    const float mu  = s * (1.f / DD);
    const float var = ss * (1.f / DD) - mu * mu;
    const float rs  = rsqrtf(var + 1e-5f);

    float4 gv = *(const float4*)(g + lane * 4);
    float4 bv = *(const float4*)(b + lane * 4);
    float4 o4;
    o4.x = (x.x - mu) * rs * gv.x + bv.x;
    o4.y = (x.y - mu) * rs * gv.y + bv.y;
    o4.z = (x.z - mu) * rs * gv.z + bv.z;
    o4.w = (x.w - mu) * rs * gv.w + bv.w;
    *(float4*)(out + (size_t)row * DD + lane * 4) = o4;
}

// ---------------------------------------------------------------------------
extern "C" void kernel_launch(void* const* d_in, const int* in_sizes, int n_in,
                              void* d_out, int out_size)
{
    const float* feat  = (const float*)d_in[0];
    const int*   src   = (const int*)  d_in[1];
    const int*   dst   = (const int*)  d_in[2];
    const float* Wq    = (const float*)d_in[3];
    const float* Wk    = (const float*)d_in[4];
    const float* Wv    = (const float*)d_in[5];
    const float* ln1_g = (const float*)d_in[6];
    const float* ln1_b = (const float*)d_in[7];
    const float* ln2_g = (const float*)d_in[8];
    const float* ln2_b = (const float*)d_in[9];
    const float* W1    = (const float*)d_in[10];
    const float* b1    = (const float*)d_in[11];
    const float* pw    = (const float*)d_in[12];
    const float* W2    = (const float*)d_in[13];
    const float* b2    = (const float*)d_in[14];
    float* out = (float*)d_out;

    __nv_bfloat16 *featb, *wqb, *wkb, *wvb, *w1b, *w2b, *qb, *kb, *vb, *rstb, *h1b;
    float *ssum, *ft2, *rst, *ffn;
    cudaGetSymbolAddress((void**)&featb, g_featb);
    cudaGetSymbolAddress((void**)&wqb,   g_wqb);
    cudaGetSymbolAddress((void**)&wkb,   g_wkb);
    cudaGetSymbolAddress((void**)&wvb,   g_wvb);
    cudaGetSymbolAddress((void**)&w1b,   g_w1b);
    cudaGetSymbolAddress((void**)&w2b,   g_w2b);
    cudaGetSymbolAddress((void**)&qb,    g_qb);
    cudaGetSymbolAddress((void**)&kb,    g_kb);
    cudaGetSymbolAddress((void**)&vb,    g_vb);
    cudaGetSymbolAddress((void**)&rstb,  g_rstb);
    cudaGetSymbolAddress((void**)&h1b,   g_h1b);
    cudaGetSymbolAddress((void**)&ssum,  g_ssum);
    cudaGetSymbolAddress((void**)&ft2,   g_ft2);
    cudaGetSymbolAddress((void**)&rst,   g_rst);
    cudaGetSymbolAddress((void**)&ffn,   g_ffn);

    // 1) zero atomic accumulators (graph replays reuse scratch)
    zero_kernel<<<2048, 256>>>(ssum, NN * HH, ft2, NN * DD);

    // 2) fp32 -> bf16 conversions (feat + weights)
    cvt_bf16_kernel<<<(NN * DD / 4 + 255) / 256, 256>>>(feat, featb, NN * DD / 4);
    cvt_bf16_kernel<<<(DD * DD / 4 + 255) / 256, 256>>>(Wq, wqb, DD * DD / 4);
    cvt_bf16_kernel<<<(DD * DD / 4 + 255) / 256, 256>>>(Wk, wkb, DD * DD / 4);
    cvt_bf16_kernel<<<(DD * DD / 4 + 255) / 256, 256>>>(Wv, wvb, DD * DD / 4);
    cvt_bf16_kernel<<<(DD * D4 / 4 + 255) / 256, 256>>>(W1, w1b, DD * D4 / 4);
    cvt_bf16_kernel<<<(D4 * DD / 4 + 255) / 256, 256>>>(W2, w2b, D4 * DD / 4);

    const int mblocks = (NN + 127) / 128;   // 313

    // 3) QKV projections (bf16 in, bf16 out)
    dim3 gqkv(DD / 64, mblocks);
    gemm_bf16<0, true><<<gqkv, 256>>>(featb, wqb, nullptr, nullptr, qb, NN, DD, DD);
    gemm_bf16<0, true><<<gqkv, 256>>>(featb, wkb, nullptr, nullptr, kb, NN, DD, DD);
    gemm_bf16<0, true><<<gqkv, 256>>>(featb, wvb, nullptr, nullptr, vb, NN, DD, DD);

    // 4) fused edge pass
    const int edge_blocks = (EE * 32 + 255) / 256;
    edge_fused_kernel<<<edge_blocks, 256>>>(qb, kb, vb, src, dst, ssum, ft2);

    // 5) rst = LN(ft2/ssum + feat)  (fp32 + bf16 outputs)
    const int ln_blocks = (NN * 32 + 255) / 256;
    ln_div_add_kernel<<<ln_blocks, 256>>>(ft2, ssum, feat, ln1_g, ln1_b, rst, rstb);

    // 6) FFN1: h1 = PReLU(rst @ W1 + b1) -> bf16
    gemm_bf16<2, true><<<dim3(D4 / 64, mblocks), 256>>>(rstb, w1b, b1, pw, h1b, NN, D4, DD);

    // 7) FFN2: ffn = h1 @ W2 + b2 -> fp32
    gemm_bf16<1, false><<<dim3(DD / 64, mblocks), 256>>>(h1b, w2b, b2, nullptr, ffn, NN, DD, D4);

    // 8) out = LN(rst + ffn)
    ln_add_kernel<<<ln_blocks, 256>>>(rst, ffn, ln2_g, ln2_b, out);
}

// round 6
// speedup vs baseline: 4.2205x; 1.3073x over previous
#include <cuda_runtime.h>
#include <cuda_bf16.h>
#include <cstdint>
#include <cstddef>

constexpr int NN = 40000;   // nodes
constexpr int EE = 640000;  // edges
constexpr int DD = 128;     // feature dim
constexpr int HH = 8;       // heads
constexpr int D4 = 512;     // FFN hidden
constexpr int QKVN = 384;   // concatenated q|k|v width

// ---------------------------------------------------------------------------
// Device scratch (zero-init .bss; no allocations anywhere)
// ---------------------------------------------------------------------------
__device__ __align__(16) __nv_bfloat16 g_featb[(size_t)NN * DD];
__device__ __align__(16) __nv_bfloat16 g_wqkvb[(size_t)DD * QKVN];
__device__ __align__(16) __nv_bfloat16 g_w1b [(size_t)DD * D4];
__device__ __align__(16) __nv_bfloat16 g_w2b [(size_t)D4 * DD];
__device__ __align__(16) __nv_bfloat16 g_qkv [(size_t)NN * QKVN];
__device__ __align__(16) __nv_bfloat16 g_rstb[(size_t)NN * DD];
__device__ __align__(16) __nv_bfloat16 g_h1b [(size_t)NN * D4];
__device__ __align__(16) float g_rst [(size_t)NN * DD];
__device__ __align__(16) float g_ffn [(size_t)NN * DD];
__device__ __align__(16) int g_hist  [NN];
__device__ __align__(16) int g_incl  [NN];
__device__ __align__(16) int g_start [NN];
__device__ __align__(16) int g_cursor[NN];
__device__ __align__(16) int g_bsum  [64];
__device__ __align__(16) int g_boff  [64];
__device__ __align__(16) int g_psrc  [EE];

// ---------------------------------------------------------------------------
// Fused prep: f32->bf16 for feat, Wq|Wk|Wv (interleaved to [128,384]), W1, W2;
// plus zero of histogram. Grid-stride over float4/int4 units.
// ---------------------------------------------------------------------------
__device__ __forceinline__ void cvt4(const float* __restrict__ in,
                                     __nv_bfloat16* __restrict__ out, int i4) {
    float4 x = *(const float4*)(in + (size_t)i4 * 4);
    __nv_bfloat162 p0 = __floats2bfloat162_rn(x.x, x.y);
    __nv_bfloat162 p1 = __floats2bfloat162_rn(x.z, x.w);
    uint2 pk; pk.x = *(uint32_t*)&p0; pk.y = *(uint32_t*)&p1;
    *(uint2*)(out + (size_t)i4 * 4) = pk;
}

constexpr int NF4 = NN * DD / 4;          // 1,280,000
constexpr int NWQ = DD * DD / 4;          // 4096
constexpr int NW1 = DD * D4 / 4;          // 16384
constexpr int NW2 = D4 * DD / 4;          // 16384
constexpr int NH4 = NN / 4;               // 10000
constexpr int C1 = NF4 + NWQ;
constexpr int C2 = C1 + NWQ;
constexpr int C3 = C2 + NWQ;
constexpr int C4 = C3 + NW1;
constexpr int C5 = C4 + NW2;
constexpr int CT = C5 + NH4;

__global__ void prep_kernel(const float* __restrict__ feat,
                            const float* __restrict__ Wq,
                            const float* __restrict__ Wk,
                            const float* __restrict__ Wv,
                            const float* __restrict__ W1,
                            const float* __restrict__ W2,
                            __nv_bfloat16* __restrict__ featb,
                            __nv_bfloat16* __restrict__ wqkvb,
                            __nv_bfloat16* __restrict__ w1b,
                            __nv_bfloat16* __restrict__ w2b,
                            int* __restrict__ hist)
{
    const int stride = gridDim.x * blockDim.x;
    for (int i = blockIdx.x * blockDim.x + threadIdx.x; i < CT; i += stride) {
        if (i < NF4) { cvt4(feat, featb, i); continue; }
        if (i < C3) {
            // QKV weight quad -> interleaved [row][3*128]
            int t, off;
            const float* W;
            if (i < C1)      { t = i - NF4; off = 0;   W = Wq; }
            else if (i < C2) { t = i - C1;  off = 128; W = Wk; }
            else             { t = i - C2;  off = 256; W = Wv; }
            const int row = t >> 5;
            const int col = (t & 31) * 4;
            float4 x = *(const float4*)(W + (size_t)t * 4);
            __nv_bfloat162 p0 = __floats2bfloat162_rn(x.x, x.y);
            __nv_bfloat162 p1 = __floats2bfloat162_rn(x.z, x.w);
            uint2 pk; pk.x = *(uint32_t*)&p0; pk.y = *(uint32_t*)&p1;
            *(uint2*)(wqkvb + (size_t)row * QKVN + off + col) = pk;
            continue;
        }
        if (i < C4) { cvt4(W1, w1b, i - C3); continue; }
        if (i < C5) { cvt4(W2, w2b, i - C4); continue; }
        ((int4*)hist)[i - C5] = make_int4(0, 0, 0, 0);
    }
}

// ---------------------------------------------------------------------------
// Counting sort by dst: histogram -> scan -> scatter(src payload)
// ---------------------------------------------------------------------------
__global__ void hist_kernel(const int* __restrict__ dst, int* __restrict__ hist)
{
    int e = blockIdx.x * blockDim.x + threadIdx.x;
    if (e < EE) atomicAdd(&hist[__ldg(dst + e)], 1);
}

constexpr int SB = 1024;
constexpr int NBLK = (NN + SB - 1) / SB;   // 40

__global__ void scan1_kernel(const int* __restrict__ hist,
                             int* __restrict__ incl, int* __restrict__ bsum)
{
    __shared__ int sh[SB];
    const int tid = threadIdx.x;
    const int i = blockIdx.x * SB + tid;
    sh[tid] = (i < NN) ? hist[i] : 0;
    __syncthreads();
#pragma unroll
    for (int off = 1; off < SB; off <<= 1) {
        int t = (tid >= off) ? sh[tid - off] : 0;
        __syncthreads();
        sh[tid] += t;
        __syncthreads();
    }
    if (i < NN) incl[i] = sh[tid];
    if (tid == SB - 1) bsum[blockIdx.x] = sh[SB - 1];
}

__global__ void scan2_kernel(const int* __restrict__ bsum, int* __restrict__ boff)
{
    __shared__ int sh[64];
    const int tid = threadIdx.x;
    int v = (tid < NBLK) ? bsum[tid] : 0;
    sh[tid] = v;
    __syncthreads();
#pragma unroll
    for (int off = 1; off < 64; off <<= 1) {
        int t = (tid >= off) ? sh[tid - off] : 0;
        __syncthreads();
        sh[tid] += t;
        __syncthreads();
    }
    if (tid < NBLK) boff[tid] = sh[tid] - v;   // exclusive
}

__global__ void scan3_kernel(const int* __restrict__ incl,
                             const int* __restrict__ hist,
                             const int* __restrict__ boff,
                             int* __restrict__ start, int* __restrict__ cursor)
{
    const int i = blockIdx.x * SB + threadIdx.x;
    if (i < NN) {
        int st = incl[i] - hist[i] + boff[blockIdx.x];
        start[i] = st;
        cursor[i] = st;
    }
}

__global__ void scatter_kernel(const int* __restrict__ src,
                               const int* __restrict__ dst,
                               int* __restrict__ cursor,
                               int* __restrict__ psrc)
{
    int e = blockIdx.x * blockDim.x + threadIdx.x;
    if (e >= EE) return;
    int pos = atomicAdd(&cursor[__ldg(dst + e)], 1);
    psrc[pos] = __ldg(src + e);
}

// ---------------------------------------------------------------------------
// BF16 tensor-core GEMM (unchanged from round 5): 128x64 tile, BK=32, 3-stage
// cp.async ring, ldmatrix fragments. MODE: 0 plain, 1 +bias, 2 +bias+PReLU.
// OUTBF: bf16 output.
// ---------------------------------------------------------------------------
__device__ __forceinline__ void mma_bf16(float* d, const uint32_t* a, const uint32_t* b) {
    asm volatile(
        "mma.sync.aligned.m16n8k16.row.col.f32.bf16.bf16.f32 "
        "{%0,%1,%2,%3}, {%4,%5,%6,%7}, {%8,%9}, {%0,%1,%2,%3};"
        : "+f"(d[0]), "+f"(d[1]), "+f"(d[2]), "+f"(d[3])
        : "r"(a[0]), "r"(a[1]), "r"(a[2]), "r"(a[3]), "r"(b[0]), "r"(b[1]));
}

__device__ __forceinline__ void ldsm_x4(uint32_t* r, const void* p) {
    uint32_t a = (uint32_t)__cvta_generic_to_shared(p);
    asm volatile("ldmatrix.sync.aligned.m8n8.x4.shared.b16 {%0,%1,%2,%3}, [%4];"
                 : "=r"(r[0]), "=r"(r[1]), "=r"(r[2]), "=r"(r[3]) : "r"(a));
}

__device__ __forceinline__ void ldsm_x4_t(uint32_t* r, const void* p) {
    uint32_t a = (uint32_t)__cvta_generic_to_shared(p);
    asm volatile("ldmatrix.sync.aligned.m8n8.x4.trans.shared.b16 {%0,%1,%2,%3}, [%4];"
                 : "=r"(r[0]), "=r"(r[1]), "=r"(r[2]), "=r"(r[3]) : "r"(a));
}

__device__ __forceinline__ void cp_async16(void* smem_dst, const void* gmem_src, int src_bytes) {
    uint32_t d = (uint32_t)__cvta_generic_to_shared(smem_dst);
    asm volatile("cp.async.ca.shared.global [%0], [%1], 16, %2;"
                 :: "r"(d), "l"(gmem_src), "r"(src_bytes));
}

template <int MODE, bool OUTBF>
__global__ void __launch_bounds__(256)
gemm_bf16(const __nv_bfloat16* __restrict__ A, const __nv_bfloat16* __restrict__ B,
          const float* __restrict__ bias, const float* __restrict__ pw,
          void* __restrict__ Cv, int M, int N, int K)
{
    constexpr int BK = 32;
    constexpr int ST = 3;
    __shared__ __nv_bfloat16 As[ST][128][BK + 8];
    __shared__ __nv_bfloat16 Bs[ST][BK][64 + 8];

    const int tid  = threadIdx.x;
    const int lane = tid & 31;
    const int warp = tid >> 5;
    const int wm   = warp >> 1;
    const int wn   = warp & 1;
    const int g    = lane >> 2;
    const int c    = lane & 3;

    const int m0 = blockIdx.y * 128;
    const int n0 = blockIdx.x * 64;

    float acc[2][4][4];
#pragma unroll
    for (int i = 0; i < 2; i++)
#pragma unroll
        for (int j = 0; j < 4; j++)
#pragma unroll
            for (int r = 0; r < 4; r++) acc[i][j][r] = 0.f;

    auto load_tile = [&](int buf, int k0) {
#pragma unroll
        for (int j = 0; j < 2; j++) {
            const int idx = tid + 256 * j;
            const int row = idx >> 2;
            const int kc8 = (idx & 3) * 8;
            cp_async16(&As[buf][row][kc8],
                       A + (size_t)(m0 + row) * K + k0 + kc8,
                       (m0 + row < M) ? 16 : 0);
        }
        {
            const int row = tid >> 3;
            const int nc8 = (tid & 7) * 8;
            cp_async16(&Bs[buf][row][nc8],
                       B + (size_t)(k0 + row) * N + n0 + nc8, 16);
        }
        asm volatile("cp.async.commit_group;" ::: "memory");
    };

    const int nk = K / BK;
    load_tile(0, 0);
    load_tile(1, BK);

    const int a_r = lane & 15;
    const int a_c = (lane >> 4) << 3;
    const int b_r = (lane & 7) + (lane & 8);
    const int b_c = (lane & 16) >> 1;

    for (int i = 0; i < nk; i++) {
        if (i < nk - 1) asm volatile("cp.async.wait_group 1;" ::: "memory");
        else            asm volatile("cp.async.wait_group 0;" ::: "memory");
        __syncthreads();

        const int nx = i + 2;
        if (nx < nk) load_tile(nx % ST, nx * BK);

        const int buf = i % ST;
#pragma unroll
        for (int chunk = 0; chunk < 2; chunk++) {
            const int kc = chunk * 16;
            uint32_t afr[2][4];
#pragma unroll
            for (int mt = 0; mt < 2; mt++)
                ldsm_x4(afr[mt], &As[buf][wm * 32 + mt * 16 + a_r][kc + a_c]);
            uint32_t bfr[2][4];
#pragma unroll
            for (int ng = 0; ng < 2; ng++)
                ldsm_x4_t(bfr[ng], &Bs[buf][kc + b_r][wn * 32 + ng * 16 + b_c]);
#pragma unroll
            for (int mt = 0; mt < 2; mt++)
#pragma unroll
                for (int ng = 0; ng < 2; ng++) {
                    mma_bf16(acc[mt][ng * 2 + 0], afr[mt], &bfr[ng][0]);
                    mma_bf16(acc[mt][ng * 2 + 1], afr[mt], &bfr[ng][2]);
                }
        }
    }

#pragma unroll
    for (int mt = 0; mt < 2; mt++) {
        const int row0 = m0 + wm * 32 + mt * 16 + g;
#pragma unroll
        for (int nt = 0; nt < 4; nt++) {
            const int col = n0 + wn * 32 + nt * 8 + 2 * c;
            float v0 = acc[mt][nt][0], v1 = acc[mt][nt][1];
            float v2 = acc[mt][nt][2], v3 = acc[mt][nt][3];
            if (MODE >= 1) {
                const float bb0 = bias[col], bb1 = bias[col + 1];
                v0 += bb0; v1 += bb1; v2 += bb0; v3 += bb1;
            }
            if (MODE == 2) {
                const float p0 = pw[col], p1 = pw[col + 1];
                v0 = (v0 >= 0.f) ? v0 : p0 * v0;
                v1 = (v1 >= 0.f) ? v1 : p1 * v1;
                v2 = (v2 >= 0.f) ? v2 : p0 * v2;
                v3 = (v3 >= 0.f) ? v3 : p1 * v3;
            }
            if (OUTBF) {
                __nv_bfloat16* Cb = (__nv_bfloat16*)Cv;
                __nv_bfloat162 p01 = __floats2bfloat162_rn(v0, v1);
                __nv_bfloat162 p23 = __floats2bfloat162_rn(v2, v3);
                if (row0 < M)     *(__nv_bfloat162*)(Cb + (size_t)row0 * N + col)       = p01;
                if (row0 + 8 < M) *(__nv_bfloat162*)(Cb + (size_t)(row0 + 8) * N + col) = p23;
            } else {
                float* Cf = (float*)Cv;
                if (row0 < M)     *(float2*)(Cf + (size_t)row0 * N + col)       = make_float2(v0, v1);
                if (row0 + 8 < M) *(float2*)(Cf + (size_t)(row0 + 8) * N + col) = make_float2(v2, v3);
            }
        }
    }
}

// ---------------------------------------------------------------------------
// FUSED per-destination aggregation + softmax-normalize + residual + LN1.
// One warp per destination node; edges pre-grouped by counting sort.
// q row loaded once; k/v gathered per edge; accumulators in registers;
// no atomics, no ft2/ssum arrays. Softmax max-shift omitted (|scores|<~0.15,
// identical after normalization). Degree-0 nodes: inv=0 -> x = feat (matches
// reference: segment_sum over empty set is 0).
// ---------------------------------------------------------------------------
__global__ void aggr_kernel(const int* __restrict__ start,
                            const int* __restrict__ endp,
                            const int* __restrict__ psrc,
                            const __nv_bfloat16* __restrict__ qkv,
                            const float* __restrict__ feat,
                            const float* __restrict__ g,
                            const float* __restrict__ b,
                            float* __restrict__ rst,
                            __nv_bfloat16* __restrict__ rstb)
{
    const int d = (int)((blockIdx.x * blockDim.x + threadIdx.x) >> 5);
    const int lane = threadIdx.x & 31;
    if (d >= NN) return;
    const int s0 = __ldg(start + d);
    const int s1 = __ldg(endp + d);

    uint2 qraw = ((const uint2*)(qkv + (size_t)d * QKVN))[lane];
    const float2 q0 = __bfloat1622float2(*(__nv_bfloat162*)&qraw.x);
    const float2 q1 = __bfloat1622float2(*(__nv_bfloat162*)&qraw.y);

    float a0 = 0.f, a1 = 0.f, a2 = 0.f, a3 = 0.f, esum = 0.f;

    int i = s0;
    for (; i + 1 < s1; i += 2) {
        const int sa = __ldg(psrc + i);
        const int sb = __ldg(psrc + i + 1);
        uint2 kra = ((const uint2*)(qkv + (size_t)sa * QKVN + 128))[lane];
        uint2 krb = ((const uint2*)(qkv + (size_t)sb * QKVN + 128))[lane];
        uint2 vra = ((const uint2*)(qkv + (size_t)sa * QKVN + 256))[lane];
        uint2 vrb = ((const uint2*)(qkv + (size_t)sb * QKVN + 256))[lane];

        float2 ka0 = __bfloat1622float2(*(__nv_bfloat162*)&kra.x);
        float2 ka1 = __bfloat1622float2(*(__nv_bfloat162*)&kra.y);
        float2 kb0 = __bfloat1622float2(*(__nv_bfloat162*)&krb.x);
        float2 kb1 = __bfloat1622float2(*(__nv_bfloat162*)&krb.y);

        float da = ka0.x * q0.x + ka0.y * q0.y + ka1.x * q1.x + ka1.y * q1.y;
        float db = kb0.x * q0.x + kb0.y * q0.y + kb1.x * q1.x + kb1.y * q1.y;
        da += __shfl_xor_sync(0xffffffffu, da, 1);
        db += __shfl_xor_sync(0xffffffffu, db, 1);
        da += __shfl_xor_sync(0xffffffffu, da, 2);
        db += __shfl_xor_sync(0xffffffffu, db, 2);
        const float exa = __expf(da * 0.08838834764831845f);
        const float exb = __expf(db * 0.08838834764831845f);
        esum += exa + exb;

        float2 va0 = __bfloat1622float2(*(__nv_bfloat162*)&vra.x);
        float2 va1 = __bfloat1622float2(*(__nv_bfloat162*)&vra.y);
        float2 vb0 = __bfloat1622float2(*(__nv_bfloat162*)&vrb.x);
        float2 vb1 = __bfloat1622float2(*(__nv_bfloat162*)&vrb.y);
        a0 += exa * va0.x + exb * vb0.x;
        a1 += exa * va0.y + exb * vb0.y;
        a2 += exa * va1.x + exb * vb1.x;
        a3 += exa * va1.y + exb * vb1.y;
    }
    if (i < s1) {
        const int sa = __ldg(psrc + i);
        uint2 kra = ((const uint2*)(qkv + (size_t)sa * QKVN + 128))[lane];
        uint2 vra = ((const uint2*)(qkv + (size_t)sa * QKVN + 256))[lane];
        float2 ka0 = __bfloat1622float2(*(__nv_bfloat162*)&kra.x);
        float2 ka1 = __bfloat1622float2(*(__nv_bfloat162*)&kra.y);
        float da = ka0.x * q0.x + ka0.y * q0.y + ka1.x * q1.x + ka1.y * q1.y;
        da += __shfl_xor_sync(0xffffffffu, da, 1);
        da += __shfl_xor_sync(0xffffffffu, da, 2);
        const float exa = __expf(da * 0.08838834764831845f);
        esum += exa;
        float2 va0 = __bfloat1622float2(*(__nv_bfloat162*)&vra.x);
        float2 va1 = __bfloat1622float2(*(__nv_bfloat162*)&vra.y);
        a0 += exa * va0.x; a1 += exa * va0.y; a2 += exa * va1.x; a3 += exa * va1.y;
    }

    const float inv = (esum > 0.f) ? (1.f / esum) : 0.f;
    float4 f = *(const float4*)(feat + (size_t)d * DD + lane * 4);
    float x0 = a0 * inv + f.x;
    float x1 = a1 * inv + f.y;
    float x2 = a2 * inv + f.z;
    float x3 = a3 * inv + f.w;

    float s  = x0 + x1 + x2 + x3;
    float ss = x0 * x0 + x1 * x1 + x2 * x2 + x3 * x3;
#pragma unroll
    for (int o = 16; o > 0; o >>= 1) {
        s  += __shfl_xor_sync(0xffffffffu, s,  o);
        ss += __shfl_xor_sync(0xffffffffu, ss, o);
    }
    const float mu  = s * (1.f / DD);
    const float var = ss * (1.f / DD) - mu * mu;
    const float rs  = rsqrtf(var + 1e-5f);

    float4 gv = *(const float4*)(g + lane * 4);
    float4 bv = *(const float4*)(b + lane * 4);
    float4 o4;
    o4.x = (x0 - mu) * rs * gv.x + bv.x;
    o4.y = (x1 - mu) * rs * gv.y + bv.y;
    o4.z = (x2 - mu) * rs * gv.z + bv.z;
    o4.w = (x3 - mu) * rs * gv.w + bv.w;
    *(float4*)(rst + (size_t)d * DD + lane * 4) = o4;

    __nv_bfloat162 p0 = __floats2bfloat162_rn(o4.x, o4.y);
    __nv_bfloat162 p1 = __floats2bfloat162_rn(o4.z, o4.w);
    uint2 pk; pk.x = *(uint32_t*)&p0; pk.y = *(uint32_t*)&p1;
    *(uint2*)(rstb + (size_t)d * DD + lane * 4) = pk;
}

// ---------------------------------------------------------------------------
// out = LN(X + Y) * g + b
// ---------------------------------------------------------------------------
__global__ void ln_add_kernel(const float* __restrict__ X,
                              const float* __restrict__ Y,
                              const float* __restrict__ g,
                              const float* __restrict__ b,
                              float* __restrict__ out)
{
    const int row = (int)((blockIdx.x * blockDim.x + threadIdx.x) >> 5);
    const int lane = threadIdx.x & 31;
    if (row >= NN) return;

    float4 x = *(const float4*)(X + (size_t)row * DD + lane * 4);
    float4 y = *(const float4*)(Y + (size_t)row * DD + lane * 4);
    x.x += y.x; x.y += y.y; x.z += y.z; x.w += y.w;

    float s  = x.x + x.y + x.z + x.w;
    float ss = x.x * x.x + x.y * x.y + x.z * x.z + x.w * x.w;
#pragma unroll
    for (int o = 16; o > 0; o >>= 1) {
        s  += __shfl_xor_sync(0xffffffffu, s,  o);
        ss += __shfl_xor_sync(0xffffffffu, ss, o);
    }
    const float mu  = s * (1.f / DD);
    const float var = ss * (1.f / DD) - mu * mu;
    const float rs  = rsqrtf(var + 1e-5f);

    float4 gv = *(const float4*)(g + lane * 4);
    float4 bv = *(const float4*)(b + lane * 4);
    float4 o4;
    o4.x = (x.x - mu) * rs * gv.x + bv.x;
    o4.y = (x.y - mu) * rs * gv.y + bv.y;
    o4.z = (x.z - mu) * rs * gv.z + bv.z;
    o4.w = (x.w - mu) * rs * gv.w + bv.w;
    *(float4*)(out + (size_t)row * DD + lane * 4) = o4;
}

// ---------------------------------------------------------------------------
extern "C" void kernel_launch(void* const* d_in, const int* in_sizes, int n_in,
                              void* d_out, int out_size)
{
    const float* feat  = (const float*)d_in[0];
    const int*   src   = (const int*)  d_in[1];
    const int*   dst   = (const int*)  d_in[2];
    const float* Wq    = (const float*)d_in[3];
    const float* Wk    = (const float*)d_in[4];
    const float* Wv    = (const float*)d_in[5];
    const float* ln1_g = (const float*)d_in[6];
    const float* ln1_b = (const float*)d_in[7];
    const float* ln2_g = (const float*)d_in[8];
    const float* ln2_b = (const float*)d_in[9];
    const float* W1    = (const float*)d_in[10];
    const float* b1    = (const float*)d_in[11];
    const float* pw    = (const float*)d_in[12];
    const float* W2    = (const float*)d_in[13];
    const float* b2    = (const float*)d_in[14];
    float* out = (float*)d_out;

    __nv_bfloat16 *featb, *wqkvb, *w1b, *w2b, *qkv, *rstb, *h1b;
    float *rst, *ffn;
    int *hist, *incl, *start, *cursor, *bsum, *boff, *psrc;
    cudaGetSymbolAddress((void**)&featb, g_featb);
    cudaGetSymbolAddress((void**)&wqkvb, g_wqkvb);
    cudaGetSymbolAddress((void**)&w1b,   g_w1b);
    cudaGetSymbolAddress((void**)&w2b,   g_w2b);
    cudaGetSymbolAddress((void**)&qkv,   g_qkv);
    cudaGetSymbolAddress((void**)&rstb,  g_rstb);
    cudaGetSymbolAddress((void**)&h1b,   g_h1b);
    cudaGetSymbolAddress((void**)&rst,   g_rst);
    cudaGetSymbolAddress((void**)&ffn,   g_ffn);
    cudaGetSymbolAddress((void**)&hist,  g_hist);
    cudaGetSymbolAddress((void**)&incl,  g_incl);
    cudaGetSymbolAddress((void**)&start, g_start);
    cudaGetSymbolAddress((void**)&cursor,g_cursor);
    cudaGetSymbolAddress((void**)&bsum,  g_bsum);
    cudaGetSymbolAddress((void**)&boff,  g_boff);
    cudaGetSymbolAddress((void**)&psrc,  g_psrc);

    // 1) fused conversions + hist zero
    prep_kernel<<<2048, 256>>>(feat, Wq, Wk, Wv, W1, W2,
                               featb, wqkvb, w1b, w2b, hist);

    const int mblocks = (NN + 127) / 128;   // 313

    // 2) QKV as one GEMM: [40000,128] @ [128,384] -> bf16 interleaved q|k|v
    gemm_bf16<0, true><<<dim3(QKVN / 64, mblocks), 256>>>(
        featb, wqkvb, nullptr, nullptr, qkv, NN, QKVN, DD);

    // 3) counting sort of edges by dst (payload = src)
    hist_kernel<<<(EE + 511) / 512, 512>>>(dst, hist);
    scan1_kernel<<<NBLK, SB>>>(hist, incl, bsum);
    scan2_kernel<<<1, 64>>>(bsum, boff);
    scan3_kernel<<<NBLK, SB>>>(incl, hist, boff, start, cursor);
    scatter_kernel<<<(EE + 511) / 512, 512>>>(src, dst, cursor, psrc);

    // 4) fused aggregation + softmax + residual + LN1 (rst fp32 + bf16)
    aggr_kernel<<<(NN * 32 + 255) / 256, 256>>>(
        start, cursor, psrc, qkv, feat, ln1_g, ln1_b, rst, rstb);

    // 5) FFN1: h1 = PReLU(rst @ W1 + b1) -> bf16
    gemm_bf16<2, true><<<dim3(D4 / 64, mblocks), 256>>>(rstb, w1b, b1, pw, h1b, NN, D4, DD);

    // 6) FFN2: ffn = h1 @ W2 + b2 -> fp32
    gemm_bf16<1, false><<<dim3(DD / 64, mblocks), 256>>>(h1b, w2b, b2, nullptr, ffn, NN, DD, D4);

    // 7) out = LN(rst + ffn)
    ln_add_kernel<<<(NN * 32 + 255) / 256, 256>>>(rst, ffn, ln2_g, ln2_b, out);
}